// round 16
// baseline (speedup 1.0000x reference)
#include <cuda_runtime.h>
#include <math.h>
#include <stdint.h>

// Problem constants
#define Bv 4
#define Sv 16
#define Nv 2048
#define Fv 32
#define Ev 16384
#define EFv 8
#define Hv 64
#define Lv 2
#define H2v 32
#define Gv (Bv*Sv)        // 64 graphs
#define SNv (Sv*Nv)       // 32768 GRU rows
#define E2v (Ev+Nv)       // 18432 edges incl self loops
#define GN (Gv*Nv)        // 131072 rows of X

// fast transcendentals (MUFU-based; abs err ~1e-6, far under 1e-3 gate)
__device__ __forceinline__ float fsigmoid(float x) {
    return __fdividef(1.f, 1.f + __expf(-x));
}
__device__ __forceinline__ float ftanh(float x) {
    float r;
    asm("tanh.approx.f32 %0, %1;" : "=f"(r) : "f"(x));
    return r;
}

// ---------------- scratch (static device globals; no allocation) ----------------
__device__ float g_X [GN*Hv];      // 33.5 MB  current node features [G][N][H]
__device__ float g_XL[GN*Hv];
__device__ float g_XR[GN*Hv];
__device__ float g_hg[GN*Hv];      // GAT output / GRU input
__device__ float g_ep[E2v*Hv];     // edge-attr projections
__device__ float g_logits[(size_t)Gv*E2v];
__device__ float g_loopattr[Nv*EFv];
__device__ int   g_deg[Nv];
__device__ int   g_rowstart[Nv+1];
__device__ int   g_cursor[Nv];
__device__ int   g_csr[Ev];
__device__ float g_Wpack[Lv*Hv*6*Hv];  // GRU weights [l][k][slot][i], slot=(ir,iz,in,hr,hz,hn)

// ---------------- preprocessing ----------------
__global__ void k_zero() {
    int idx = blockIdx.x*blockDim.x + threadIdx.x;
    if (idx < Nv) { g_deg[idx] = 0; g_cursor[idx] = 0; }
}

__global__ void k_deg(const int* __restrict__ ei) {
    int e = blockIdx.x*blockDim.x + threadIdx.x;
    if (e >= Ev) return;
    atomicAdd(&g_deg[ei[Ev + e]], 1);
}

__global__ void k_scan() {  // 1 block, 1024 threads: exclusive scan of deg -> rowstart
    __shared__ int s[1024];
    int t = threadIdx.x;
    int a = g_deg[2*t], b = g_deg[2*t+1];
    s[t] = a + b;
    __syncthreads();
    for (int off = 1; off < 1024; off <<= 1) {
        int v = (t >= off) ? s[t-off] : 0;
        __syncthreads();
        s[t] += v;
        __syncthreads();
    }
    int excl = s[t] - (a + b);
    g_rowstart[2*t]   = excl;
    g_rowstart[2*t+1] = excl + a;
    if (t == 1023) g_rowstart[2048] = s[1023];
}

__global__ void k_fill_csr(const int* __restrict__ ei) {
    int e = blockIdx.x*blockDim.x + threadIdx.x;
    if (e >= Ev) return;
    int d = ei[Ev + e];
    int pos = atomicAdd(&g_cursor[d], 1);
    g_csr[g_rowstart[d] + pos] = e;
}

// canonicalize CSR row order -> fully deterministic reduction order downstream
__global__ void k_sort_csr() {
    int n = blockIdx.x*blockDim.x + threadIdx.x;
    if (n >= Nv) return;
    int rs = g_rowstart[n], re = g_rowstart[n+1];
    for (int j = rs + 1; j < re; j++) {
        int v = g_csr[j];
        int k = j - 1;
        while (k >= rs && g_csr[k] > v) { g_csr[k+1] = g_csr[k]; k--; }
        g_csr[k+1] = v;
    }
}

// self-loop attr = mean of incoming edge attrs (deterministic: sorted CSR order)
__global__ void k_loopattr(const float* __restrict__ ea) {
    int idx = blockIdx.x*blockDim.x + threadIdx.x;   // Nv*EFv = 16384
    if (idx >= Nv*EFv) return;
    int n = idx >> 3, f = idx & 7;
    int rs = g_rowstart[n], re = g_rowstart[n+1];
    float s = 0.f;
    for (int j = rs; j < re; j++) s += ea[(size_t)g_csr[j]*EFv + f];
    g_loopattr[idx] = s / fmaxf((float)(re - rs), 1.f);
}

// pack GRU weights k-major with i contiguous per slot: [l][k][slot][i]
__global__ void k_pack_gru(const float* __restrict__ Wih, const float* __restrict__ Whh) {
    int idx = blockIdx.x*blockDim.x + threadIdx.x;   // L*H*H = 8192
    if (idx >= Lv*Hv*Hv) return;
    int l = idx >> 12, rem = idx & 4095, k = rem >> 6, i = rem & 63;
    float* dst = g_Wpack + (((size_t)l*Hv + k)*6)*Hv + i;
    #pragma unroll
    for (int gate = 0; gate < 3; gate++) {
        dst[gate*Hv]       = Wih[l*192*64 + (gate*64 + i)*64 + k];
        dst[(3+gate)*Hv]   = Whh[l*192*64 + (gate*64 + i)*64 + k];
    }
}

// ---------------- X = x @ Wp + bp  (32 rows/block, 8 rows/thread) ----------------
__global__ void k_proj(const float* __restrict__ x, const float* __restrict__ Wp,
                       const float* __restrict__ bp) {
    __shared__ float sW[Fv*Hv];      // 8 KB
    __shared__ float sx[32][Fv];     // 4 KB
    int tid = threadIdx.x;
    for (int j = tid; j < Fv*Hv; j += 256) sW[j] = Wp[j];
    size_t row0 = (size_t)blockIdx.x * 32;
    for (int j = tid; j < 32*Fv; j += 256) sx[j>>5][j&31] = x[row0*Fv + j];
    __syncthreads();
    int tr = tid >> 6, i = tid & 63;
    float bv = bp[i];
    float acc[8];
    #pragma unroll
    for (int r = 0; r < 8; r++) acc[r] = bv;
    for (int k = 0; k < Fv; k++) {
        float wv = sW[k*Hv + i];
        #pragma unroll
        for (int r = 0; r < 8; r++) acc[r] += sx[tr*8 + r][k] * wv;
    }
    #pragma unroll
    for (int r = 0; r < 8; r++) g_X[(row0 + tr*8 + r)*Hv + i] = acc[r];
}

// ---------------- generic 64x64 linear: (dst?g_XR:g_XL) = g_X @ W + b ----------------
// Split from the fused XL/XR kernel: 24KB smem/block -> 8 blocks/SM -> 100% occ.
// Destination selected ON DEVICE (passing __device__ globals from host is invalid).
// Same thread mapping + k-ascending accumulation order as the fused version.
__global__ void k_lin64(const float* __restrict__ W, const float* __restrict__ b,
                        int dst, int l) {
    __shared__ float sW[Hv*Hv];      // 16 KB  (k-major: [k][i])
    __shared__ float sx[32][Hv];     // 8 KB
    float* __restrict__ OUT = dst ? g_XR : g_XL;
    int tid = threadIdx.x;
    for (int j = tid; j < Hv*Hv; j += 256) sW[j] = W[l*Hv*Hv + j];
    size_t row0 = (size_t)blockIdx.x * 32;
    for (int j = tid; j < 32*Hv; j += 256) sx[j>>6][j&63] = g_X[row0*Hv + j];
    __syncthreads();
    int tr = tid >> 6, i = tid & 63;
    float bv = b[l*Hv + i];
    float acc[8];
    #pragma unroll
    for (int r = 0; r < 8; r++) acc[r] = bv;
    for (int k4 = 0; k4 < Hv; k4 += 4) {
        float4 xq[8];
        #pragma unroll
        for (int r = 0; r < 8; r++) xq[r] = *(const float4*)&sx[tr*8 + r][k4];
        #pragma unroll
        for (int kk = 0; kk < 4; kk++) {
            float wv = sW[(k4+kk)*Hv + i];
            #pragma unroll
            for (int r = 0; r < 8; r++)
                acc[r] += ((const float*)&xq[r])[kk] * wv;
        }
    }
    #pragma unroll
    for (int r = 0; r < 8; r++)
        OUT[(row0 + tr*8 + r)*Hv + i] = acc[r];
}

// ---------------- ep = ea_f @ We[l] ----------------
__global__ void k_ep(const float* __restrict__ ea, const float* __restrict__ We, int l) {
    int idx = blockIdx.x*blockDim.x + threadIdx.x;   // E2*H
    int e2 = idx >> 6, i = idx & 63;
    const float* a = (e2 < Ev) ? (ea + (size_t)e2*EFv) : (g_loopattr + (size_t)(e2 - Ev)*EFv);
    float acc = 0.f;
    #pragma unroll
    for (int f = 0; f < EFv; f++) acc += a[f] * We[l*EFv*Hv + f*Hv + i];
    g_ep[idx] = acc;
}

// ---------------- attention logits, warp per (g,e): edge-parallel ----------------
__global__ void k_logits(const int* __restrict__ ei, const float* __restrict__ att, int l) {
    int w = (blockIdx.x*blockDim.x + threadIdx.x) >> 5;
    int lane = threadIdx.x & 31;
    int g = w / E2v;
    int e = w - g*E2v;
    int sn, dn;
    if (e < Ev) { sn = ei[e]; dn = ei[Ev + e]; } else { sn = dn = e - Ev; }
    const float* xl = g_XL + ((size_t)g*Nv + sn)*Hv;
    const float* xr = g_XR + ((size_t)g*Nv + dn)*Hv;
    const float* ep = g_ep + (size_t)e*Hv;
    float acc = 0.f;
    #pragma unroll
    for (int c = 0; c < 2; c++) {
        int h = lane + 32*c;
        float m = xl[h] + xr[h] + ep[h];
        m = (m > 0.f) ? m : 0.2f*m;      // leaky_relu(0.2)
        acc += m * att[l*Hv + h];
    }
    #pragma unroll
    for (int o = 16; o; o >>= 1) acc += __shfl_xor_sync(0xffffffffu, acc, o);
    if (lane == 0) g_logits[(size_t)g*E2v + e] = acc;
}

// ---------------- softmax + aggregate, warp per (g,n) ----------------
__global__ void k_aggr(const int* __restrict__ ei, const float* __restrict__ gb, int l) {
    int w = (blockIdx.x*blockDim.x + threadIdx.x) >> 5;
    int lane = threadIdx.x & 31;
    int g = w >> 11;           // / N
    int n = w & (Nv-1);
    const float* lg = g_logits + (size_t)g*E2v;
    int rs = g_rowstart[n], re = g_rowstart[n+1];
    float lself = lg[Ev + n];
    float lmax = lself;
    for (int j = rs; j < re; j++) lmax = fmaxf(lmax, lg[g_csr[j]]);
    float psum, acc0, acc1;
    {
        float p = __expf(lself - lmax);
        const float* xl = g_XL + ((size_t)g*Nv + n)*Hv;
        psum = p; acc0 = p*xl[lane]; acc1 = p*xl[lane+32];
    }
    for (int j = rs; j < re; j++) {
        int e = g_csr[j];
        int s = ei[e];
        float p = __expf(lg[e] - lmax);
        const float* xl = g_XL + ((size_t)g*Nv + s)*Hv;
        psum += p; acc0 += p*xl[lane]; acc1 += p*xl[lane+32];
    }
    float inv = __fdividef(1.f, psum);
    size_t o = ((size_t)g*Nv + n)*Hv;
    g_hg[o + lane]      = acc0*inv + gb[l*Hv + lane];
    g_hg[o + lane + 32] = acc1*inv + gb[l*Hv + lane + 32];
}

// ---------------- GRU layer: scan over T=B=4, 16 rows/block ----------------
// coalesced scalar weight loads ([k][slot][i]) + broadcast LDS.128 for x/h.
__global__ void k_gru(const float* __restrict__ bih, const float* __restrict__ bhh, int l) {
    __shared__ float sx[16][Hv];
    __shared__ float sh[16][Hv];
    int tid = threadIdx.x;
    int tr = tid >> 6, i = tid & 63;
    int mb = blockIdx.x * 16;
    for (int r = tr; r < 16; r += 4) sh[r][i] = 0.f;
    float bi0 = bih[l*192 + i], bi1 = bih[l*192 + 64 + i], bi2 = bih[l*192 + 128 + i];
    float bh0 = bhh[l*192 + i], bh1 = bhh[l*192 + 64 + i], bh2 = bhh[l*192 + 128 + i];
    const float* __restrict__ wbase = g_Wpack + (size_t)l*Hv*6*Hv + i;
    __syncthreads();
    for (int t = 0; t < Bv; t++) {
        for (int r = tr; r < 16; r += 4)
            sx[r][i] = g_hg[((size_t)t*SNv + mb + r)*Hv + i];
        __syncthreads();
        float a0[4], a1[4], a2[4], c0[4], c1[4], c2[4];
        #pragma unroll
        for (int r = 0; r < 4; r++) { a0[r]=bi0; a1[r]=bi1; a2[r]=bi2; c0[r]=bh0; c1[r]=bh1; c2[r]=bh2; }
        for (int k4 = 0; k4 < Hv; k4 += 4) {
            float4 xq[4], hq[4];
            #pragma unroll
            for (int r = 0; r < 4; r++) {
                int row = tr*4 + r;
                xq[r] = *(const float4*)&sx[row][k4];
                hq[r] = *(const float4*)&sh[row][k4];
            }
            #pragma unroll
            for (int kk = 0; kk < 4; kk++) {
                const float* w = wbase + (size_t)(k4+kk)*6*Hv;
                float w0 = w[0],      w1 = w[Hv],     w2 = w[2*Hv];
                float w3 = w[3*Hv],   w4 = w[4*Hv],   w5 = w[5*Hv];
                #pragma unroll
                for (int r = 0; r < 4; r++) {
                    float xv = ((const float*)&xq[r])[kk];
                    float hv = ((const float*)&hq[r])[kk];
                    a0[r] += xv*w0; a1[r] += xv*w1; a2[r] += xv*w2;
                    c0[r] += hv*w3; c1[r] += hv*w4; c2[r] += hv*w5;
                }
            }
        }
        float hnew[4];
        #pragma unroll
        for (int r = 0; r < 4; r++) {
            int row = tr*4 + r;
            float rg = fsigmoid(a0[r] + c0[r]);
            float zg = fsigmoid(a1[r] + c1[r]);
            float ng = ftanh(a2[r] + rg*c2[r]);
            hnew[r] = (1.f - zg)*ng + zg*sh[row][i];
        }
        __syncthreads();
        #pragma unroll
        for (int r = 0; r < 4; r++) {
            int row = tr*4 + r;
            sh[row][i] = hnew[r];
            g_X[((size_t)t*SNv + mb + row)*Hv + i] = hnew[r];
        }
        __syncthreads();
    }
}

// ---------------- output heads, warp per (b,n) row ----------------
__global__ void k_heads(const float* __restrict__ oW1, const float* __restrict__ ob1,
                        const float* __restrict__ oW2, const float* __restrict__ ob2,
                        const float* __restrict__ dW1, const float* __restrict__ db1,
                        const float* __restrict__ dW2, const float* __restrict__ db2,
                        float* __restrict__ out) {
    int w = (blockIdx.x*blockDim.x + threadIdx.x) >> 5;
    int lane = threadIdx.x & 31;
    int b = w >> 11, n = w & (Nv-1);
    const float* xl = g_X + (((size_t)(b*Sv + (Sv-1)))*Nv + n)*Hv;
    float x0 = xl[lane], x1 = xl[lane+32];
    float ho = ob1[lane], hd = db1[lane];
    for (int k = 0; k < Hv; k++) {
        float xv = __shfl_sync(0xffffffffu, (k < 32) ? x0 : x1, k & 31);
        ho += xv * oW1[k*H2v + lane];
        hd += xv * dW1[k*H2v + lane];
    }
    ho = fmaxf(ho, 0.f);
    hd = fmaxf(hd, 0.f);
    float so = ho * oW2[lane];
    float sd = hd * dW2[lane];
    #pragma unroll
    for (int o = 16; o; o >>= 1) {
        so += __shfl_xor_sync(0xffffffffu, so, o);
        sd += __shfl_xor_sync(0xffffffffu, sd, o);
    }
    if (lane == 0) {
        out[w]          = so + ob2[0];
        out[Bv*Nv + w]  = sd + db2[0];
    }
}

// ---------------- launcher ----------------
// ncu capture lands on the 4th launch: slot 4 = k_lin64 (XL, l=0) to verify
// the occupancy prediction. Dataflow unchanged.
extern "C" void kernel_launch(void* const* d_in, const int* in_sizes, int n_in,
                              void* d_out, int out_size) {
    const float* x   = (const float*)d_in[0];
    const int*   ei  = (const int*)  d_in[1];
    const float* ea  = (const float*)d_in[2];
    const float* Wp  = (const float*)d_in[3];
    const float* bp  = (const float*)d_in[4];
    const float* Wl  = (const float*)d_in[5];
    const float* bl  = (const float*)d_in[6];
    const float* Wr  = (const float*)d_in[7];
    const float* br  = (const float*)d_in[8];
    const float* We  = (const float*)d_in[9];
    const float* att = (const float*)d_in[10];
    const float* gb  = (const float*)d_in[11];
    const float* Wih = (const float*)d_in[12];
    const float* Whh = (const float*)d_in[13];
    const float* bih = (const float*)d_in[14];
    const float* bhh = (const float*)d_in[15];
    const float* oW1 = (const float*)d_in[16];
    const float* ob1 = (const float*)d_in[17];
    const float* oW2 = (const float*)d_in[18];
    const float* ob2 = (const float*)d_in[19];
    const float* dW1 = (const float*)d_in[20];
    const float* db1 = (const float*)d_in[21];
    const float* dW2 = (const float*)d_in[22];
    const float* db2 = (const float*)d_in[23];
    float* out = (float*)d_out;

    // 1-3: input-only deps
    k_proj    <<<GN/32, 256>>>(x, Wp, bp);
    k_pack_gru<<<32, 256>>>(Wih, Whh);
    k_zero    <<<8, 256>>>();
    // 4: layer-0 XL projection  <-- ncu capture target
    k_lin64   <<<GN/32, 256>>>(Wl, bl, 0, 0);
    k_lin64   <<<GN/32, 256>>>(Wr, br, 1, 0);
    // deterministic CSR + loop attrs
    k_deg     <<<64, 256>>>(ei);
    k_scan    <<<1, 1024>>>();
    k_fill_csr<<<64, 256>>>(ei);
    k_sort_csr<<<8, 256>>>();
    k_loopattr<<<64, 256>>>(ea);

    for (int l = 0; l < Lv; l++) {
        if (l > 0) {
            k_lin64<<<GN/32, 256>>>(Wl, bl, 0, l);
            k_lin64<<<GN/32, 256>>>(Wr, br, 1, l);
        }
        k_ep    <<<E2v*Hv/256, 256>>>(ea, We, l);
        k_logits<<<(int)((size_t)Gv*E2v*32/256), 256>>>(ei, att, l);
        k_aggr  <<<GN*32/256, 256>>>(ei, gb, l);
        k_gru   <<<SNv/16, 256>>>(bih, bhh, l);
    }

    k_heads<<<Bv*Nv*32/256, 256>>>(oW1, ob1, oW2, ob2, dW1, db1, dW2, db2, out);
}

// round 17
// speedup vs baseline: 1.0908x; 1.0908x over previous
#include <cuda_runtime.h>
#include <math.h>
#include <stdint.h>

// Problem constants
#define Bv 4
#define Sv 16
#define Nv 2048
#define Fv 32
#define Ev 16384
#define EFv 8
#define Hv 64
#define Lv 2
#define H2v 32
#define Gv (Bv*Sv)        // 64 graphs
#define SNv (Sv*Nv)       // 32768 GRU rows
#define E2v (Ev+Nv)       // 18432 edges incl self loops
#define GN (Gv*Nv)        // 131072 rows of X

// fast transcendentals (MUFU-based; abs err ~1e-6, far under 1e-3 gate)
__device__ __forceinline__ float fsigmoid(float x) {
    return __fdividef(1.f, 1.f + __expf(-x));
}
__device__ __forceinline__ float ftanh(float x) {
    float r;
    asm("tanh.approx.f32 %0, %1;" : "=f"(r) : "f"(x));
    return r;
}

// ---------------- scratch (static device globals; no allocation) ----------------
__device__ float g_X [GN*Hv];      // 33.5 MB  current node features [G][N][H]
__device__ float g_XL[GN*Hv];
__device__ float g_XR[GN*Hv];
__device__ float g_hg[GN*Hv];      // GAT output / GRU input
__device__ float g_ep[E2v*Hv];     // edge-attr projections
__device__ float g_logits[(size_t)Gv*E2v];
__device__ float g_loopattr[Nv*EFv];
__device__ int   g_deg[Nv];
__device__ int   g_rowstart[Nv+1];
__device__ int   g_cursor[Nv];
__device__ int   g_csr[Ev];
__device__ float g_Wpack[Lv*Hv*6*Hv];  // GRU weights [l][k][slot][i], slot=(ir,iz,in,hr,hz,hn)

// ---------------- preprocessing ----------------
__global__ void k_zero() {
    int idx = blockIdx.x*blockDim.x + threadIdx.x;
    if (idx < Nv) { g_deg[idx] = 0; g_cursor[idx] = 0; }
}

__global__ void k_deg(const int* __restrict__ ei) {
    int e = blockIdx.x*blockDim.x + threadIdx.x;
    if (e >= Ev) return;
    atomicAdd(&g_deg[ei[Ev + e]], 1);
}

__global__ void k_scan() {  // 1 block, 1024 threads: exclusive scan of deg -> rowstart
    __shared__ int s[1024];
    int t = threadIdx.x;
    int a = g_deg[2*t], b = g_deg[2*t+1];
    s[t] = a + b;
    __syncthreads();
    for (int off = 1; off < 1024; off <<= 1) {
        int v = (t >= off) ? s[t-off] : 0;
        __syncthreads();
        s[t] += v;
        __syncthreads();
    }
    int excl = s[t] - (a + b);
    g_rowstart[2*t]   = excl;
    g_rowstart[2*t+1] = excl + a;
    if (t == 1023) g_rowstart[2048] = s[1023];
}

__global__ void k_fill_csr(const int* __restrict__ ei) {
    int e = blockIdx.x*blockDim.x + threadIdx.x;
    if (e >= Ev) return;
    int d = ei[Ev + e];
    int pos = atomicAdd(&g_cursor[d], 1);
    g_csr[g_rowstart[d] + pos] = e;
}

// canonicalize CSR row order -> fully deterministic reduction order downstream
__global__ void k_sort_csr() {
    int n = blockIdx.x*blockDim.x + threadIdx.x;
    if (n >= Nv) return;
    int rs = g_rowstart[n], re = g_rowstart[n+1];
    for (int j = rs + 1; j < re; j++) {
        int v = g_csr[j];
        int k = j - 1;
        while (k >= rs && g_csr[k] > v) { g_csr[k+1] = g_csr[k]; k--; }
        g_csr[k+1] = v;
    }
}

// self-loop attr = mean of incoming edge attrs (deterministic: sorted CSR order)
__global__ void k_loopattr(const float* __restrict__ ea) {
    int idx = blockIdx.x*blockDim.x + threadIdx.x;   // Nv*EFv = 16384
    if (idx >= Nv*EFv) return;
    int n = idx >> 3, f = idx & 7;
    int rs = g_rowstart[n], re = g_rowstart[n+1];
    float s = 0.f;
    for (int j = rs; j < re; j++) s += ea[(size_t)g_csr[j]*EFv + f];
    g_loopattr[idx] = s / fmaxf((float)(re - rs), 1.f);
}

// pack GRU weights k-major with i contiguous per slot: [l][k][slot][i]
__global__ void k_pack_gru(const float* __restrict__ Wih, const float* __restrict__ Whh) {
    int idx = blockIdx.x*blockDim.x + threadIdx.x;   // L*H*H = 8192
    if (idx >= Lv*Hv*Hv) return;
    int l = idx >> 12, rem = idx & 4095, k = rem >> 6, i = rem & 63;
    float* dst = g_Wpack + (((size_t)l*Hv + k)*6)*Hv + i;
    #pragma unroll
    for (int gate = 0; gate < 3; gate++) {
        dst[gate*Hv]       = Wih[l*192*64 + (gate*64 + i)*64 + k];
        dst[(3+gate)*Hv]   = Whh[l*192*64 + (gate*64 + i)*64 + k];
    }
}

// ---------------- X = x @ Wp + bp  (32 rows/block, 8 rows/thread) ----------------
__global__ void k_proj(const float* __restrict__ x, const float* __restrict__ Wp,
                       const float* __restrict__ bp) {
    __shared__ float sW[Fv*Hv];      // 8 KB
    __shared__ float sx[32][Fv];     // 4 KB
    int tid = threadIdx.x;
    for (int j = tid; j < Fv*Hv; j += 256) sW[j] = Wp[j];
    size_t row0 = (size_t)blockIdx.x * 32;
    for (int j = tid; j < 32*Fv; j += 256) sx[j>>5][j&31] = x[row0*Fv + j];
    __syncthreads();
    int tr = tid >> 6, i = tid & 63;
    float bv = bp[i];
    float acc[8];
    #pragma unroll
    for (int r = 0; r < 8; r++) acc[r] = bv;
    for (int k = 0; k < Fv; k++) {
        float wv = sW[k*Hv + i];
        #pragma unroll
        for (int r = 0; r < 8; r++) acc[r] += sx[tr*8 + r][k] * wv;
    }
    #pragma unroll
    for (int r = 0; r < 8; r++) g_X[(row0 + tr*8 + r)*Hv + i] = acc[r];
}

// ---------------- XL/XR projections (fused, R14-exact: best measured) ----------------
__global__ void k_xlxr(const float* __restrict__ Wl, const float* __restrict__ bl,
                       const float* __restrict__ Wr, const float* __restrict__ br, int l) {
    __shared__ float sWl[Hv*Hv];     // 16 KB
    __shared__ float sWr[Hv*Hv];     // 16 KB
    __shared__ float sx[32][Hv];     // 8 KB
    int tid = threadIdx.x;
    for (int j = tid; j < Hv*Hv; j += 256) { sWl[j] = Wl[l*Hv*Hv + j]; sWr[j] = Wr[l*Hv*Hv + j]; }
    size_t row0 = (size_t)blockIdx.x * 32;
    for (int j = tid; j < 32*Hv; j += 256) sx[j>>6][j&63] = g_X[row0*Hv + j];
    __syncthreads();
    int tr = tid >> 6, i = tid & 63;
    float blv = bl[l*Hv + i], brv = br[l*Hv + i];
    float aL[8], aR[8];
    #pragma unroll
    for (int r = 0; r < 8; r++) { aL[r] = blv; aR[r] = brv; }
    for (int k4 = 0; k4 < Hv; k4 += 4) {
        float4 xq[8];
        #pragma unroll
        for (int r = 0; r < 8; r++) xq[r] = *(const float4*)&sx[tr*8 + r][k4];
        #pragma unroll
        for (int kk = 0; kk < 4; kk++) {
            float wl = sWl[(k4+kk)*Hv + i], wr = sWr[(k4+kk)*Hv + i];
            #pragma unroll
            for (int r = 0; r < 8; r++) {
                float xv = ((const float*)&xq[r])[kk];
                aL[r] += xv * wl;
                aR[r] += xv * wr;
            }
        }
    }
    #pragma unroll
    for (int r = 0; r < 8; r++) {
        size_t row = row0 + tr*8 + r;
        g_XL[row*Hv + i] = aL[r];
        g_XR[row*Hv + i] = aR[r];
    }
}

// ---------------- ep = ea_f @ We[l] ----------------
__global__ void k_ep(const float* __restrict__ ea, const float* __restrict__ We, int l) {
    int idx = blockIdx.x*blockDim.x + threadIdx.x;   // E2*H
    int e2 = idx >> 6, i = idx & 63;
    const float* a = (e2 < Ev) ? (ea + (size_t)e2*EFv) : (g_loopattr + (size_t)(e2 - Ev)*EFv);
    float acc = 0.f;
    #pragma unroll
    for (int f = 0; f < EFv; f++) acc += a[f] * We[l*EFv*Hv + f*Hv + i];
    g_ep[idx] = acc;
}

// ---------------- attention logits, warp per (g,e): edge-parallel ----------------
__global__ void k_logits(const int* __restrict__ ei, const float* __restrict__ att, int l) {
    int w = (blockIdx.x*blockDim.x + threadIdx.x) >> 5;
    int lane = threadIdx.x & 31;
    int g = w / E2v;
    int e = w - g*E2v;
    int sn, dn;
    if (e < Ev) { sn = ei[e]; dn = ei[Ev + e]; } else { sn = dn = e - Ev; }
    const float* xl = g_XL + ((size_t)g*Nv + sn)*Hv;
    const float* xr = g_XR + ((size_t)g*Nv + dn)*Hv;
    const float* ep = g_ep + (size_t)e*Hv;
    float acc = 0.f;
    #pragma unroll
    for (int c = 0; c < 2; c++) {
        int h = lane + 32*c;
        float m = xl[h] + xr[h] + ep[h];
        m = (m > 0.f) ? m : 0.2f*m;      // leaky_relu(0.2)
        acc += m * att[l*Hv + h];
    }
    #pragma unroll
    for (int o = 16; o; o >>= 1) acc += __shfl_xor_sync(0xffffffffu, acc, o);
    if (lane == 0) g_logits[(size_t)g*E2v + e] = acc;
}

// ---------------- softmax + aggregate, warp per (g,n) ----------------
__global__ void k_aggr(const int* __restrict__ ei, const float* __restrict__ gb, int l) {
    int w = (blockIdx.x*blockDim.x + threadIdx.x) >> 5;
    int lane = threadIdx.x & 31;
    int g = w >> 11;           // / N
    int n = w & (Nv-1);
    const float* lg = g_logits + (size_t)g*E2v;
    int rs = g_rowstart[n], re = g_rowstart[n+1];
    float lself = lg[Ev + n];
    float lmax = lself;
    for (int j = rs; j < re; j++) lmax = fmaxf(lmax, lg[g_csr[j]]);
    float psum, acc0, acc1;
    {
        float p = __expf(lself - lmax);
        const float* xl = g_XL + ((size_t)g*Nv + n)*Hv;
        psum = p; acc0 = p*xl[lane]; acc1 = p*xl[lane+32];
    }
    for (int j = rs; j < re; j++) {
        int e = g_csr[j];
        int s = ei[e];
        float p = __expf(lg[e] - lmax);
        const float* xl = g_XL + ((size_t)g*Nv + s)*Hv;
        psum += p; acc0 += p*xl[lane]; acc1 += p*xl[lane+32];
    }
    float inv = __fdividef(1.f, psum);
    size_t o = ((size_t)g*Nv + n)*Hv;
    g_hg[o + lane]      = acc0*inv + gb[l*Hv + lane];
    g_hg[o + lane + 32] = acc1*inv + gb[l*Hv + lane + 32];
}

// ---------------- GRU layer: scan over T=B=4, 16 rows/block ----------------
// t=0 specialized: h==0, so the h-GEMM contributes exact zeros -> skip it
// (bitwise-identical output, ~1/8 of total GRU work removed).
__global__ void k_gru(const float* __restrict__ bih, const float* __restrict__ bhh, int l) {
    __shared__ float sx[16][Hv];
    __shared__ float sh[16][Hv];
    int tid = threadIdx.x;
    int tr = tid >> 6, i = tid & 63;
    int mb = blockIdx.x * 16;
    float bi0 = bih[l*192 + i], bi1 = bih[l*192 + 64 + i], bi2 = bih[l*192 + 128 + i];
    float bh0 = bhh[l*192 + i], bh1 = bhh[l*192 + 64 + i], bh2 = bhh[l*192 + 128 + i];
    const float* __restrict__ wbase = g_Wpack + (size_t)l*Hv*6*Hv + i;

    // ---- t = 0: h == 0 ----
    for (int r = tr; r < 16; r += 4)
        sx[r][i] = g_hg[((size_t)(mb + r))*Hv + i];
    __syncthreads();
    {
        float a0[4], a1[4], a2[4];
        #pragma unroll
        for (int r = 0; r < 4; r++) { a0[r]=bi0; a1[r]=bi1; a2[r]=bi2; }
        for (int k4 = 0; k4 < Hv; k4 += 4) {
            float4 xq[4];
            #pragma unroll
            for (int r = 0; r < 4; r++) xq[r] = *(const float4*)&sx[tr*4 + r][k4];
            #pragma unroll
            for (int kk = 0; kk < 4; kk++) {
                const float* w = wbase + (size_t)(k4+kk)*6*Hv;
                float w0 = w[0], w1 = w[Hv], w2 = w[2*Hv];
                #pragma unroll
                for (int r = 0; r < 4; r++) {
                    float xv = ((const float*)&xq[r])[kk];
                    a0[r] += xv*w0; a1[r] += xv*w1; a2[r] += xv*w2;
                }
            }
        }
        __syncthreads();   // sx fully consumed before sh writes / next sx load
        #pragma unroll
        for (int r = 0; r < 4; r++) {
            int row = tr*4 + r;
            float rg = fsigmoid(a0[r] + bh0);
            float zg = fsigmoid(a1[r] + bh1);
            float ng = ftanh(a2[r] + rg*bh2);
            float hnew = (1.f - zg)*ng;    // + zg*0 exactly
            sh[row][i] = hnew;
            g_X[((size_t)(mb + row))*Hv + i] = hnew;
        }
        __syncthreads();
    }

    // ---- t = 1..3 ----
    for (int t = 1; t < Bv; t++) {
        for (int r = tr; r < 16; r += 4)
            sx[r][i] = g_hg[((size_t)t*SNv + mb + r)*Hv + i];
        __syncthreads();
        float a0[4], a1[4], a2[4], c0[4], c1[4], c2[4];
        #pragma unroll
        for (int r = 0; r < 4; r++) { a0[r]=bi0; a1[r]=bi1; a2[r]=bi2; c0[r]=bh0; c1[r]=bh1; c2[r]=bh2; }
        for (int k4 = 0; k4 < Hv; k4 += 4) {
            float4 xq[4], hq[4];
            #pragma unroll
            for (int r = 0; r < 4; r++) {
                int row = tr*4 + r;
                xq[r] = *(const float4*)&sx[row][k4];
                hq[r] = *(const float4*)&sh[row][k4];
            }
            #pragma unroll
            for (int kk = 0; kk < 4; kk++) {
                const float* w = wbase + (size_t)(k4+kk)*6*Hv;
                float w0 = w[0],      w1 = w[Hv],     w2 = w[2*Hv];
                float w3 = w[3*Hv],   w4 = w[4*Hv],   w5 = w[5*Hv];
                #pragma unroll
                for (int r = 0; r < 4; r++) {
                    float xv = ((const float*)&xq[r])[kk];
                    float hv = ((const float*)&hq[r])[kk];
                    a0[r] += xv*w0; a1[r] += xv*w1; a2[r] += xv*w2;
                    c0[r] += hv*w3; c1[r] += hv*w4; c2[r] += hv*w5;
                }
            }
        }
        float hnew[4];
        #pragma unroll
        for (int r = 0; r < 4; r++) {
            int row = tr*4 + r;
            float rg = fsigmoid(a0[r] + c0[r]);
            float zg = fsigmoid(a1[r] + c1[r]);
            float ng = ftanh(a2[r] + rg*c2[r]);
            hnew[r] = (1.f - zg)*ng + zg*sh[row][i];
        }
        __syncthreads();
        #pragma unroll
        for (int r = 0; r < 4; r++) {
            int row = tr*4 + r;
            sh[row][i] = hnew[r];
            g_X[((size_t)t*SNv + mb + row)*Hv + i] = hnew[r];
        }
        __syncthreads();
    }
}

// ---------------- output heads, warp per (b,n) row ----------------
__global__ void k_heads(const float* __restrict__ oW1, const float* __restrict__ ob1,
                        const float* __restrict__ oW2, const float* __restrict__ ob2,
                        const float* __restrict__ dW1, const float* __restrict__ db1,
                        const float* __restrict__ dW2, const float* __restrict__ db2,
                        float* __restrict__ out) {
    int w = (blockIdx.x*blockDim.x + threadIdx.x) >> 5;
    int lane = threadIdx.x & 31;
    int b = w >> 11, n = w & (Nv-1);
    const float* xl = g_X + (((size_t)(b*Sv + (Sv-1)))*Nv + n)*Hv;
    float x0 = xl[lane], x1 = xl[lane+32];
    float ho = ob1[lane], hd = db1[lane];
    for (int k = 0; k < Hv; k++) {
        float xv = __shfl_sync(0xffffffffu, (k < 32) ? x0 : x1, k & 31);
        ho += xv * oW1[k*H2v + lane];
        hd += xv * dW1[k*H2v + lane];
    }
    ho = fmaxf(ho, 0.f);
    hd = fmaxf(hd, 0.f);
    float so = ho * oW2[lane];
    float sd = hd * dW2[lane];
    #pragma unroll
    for (int o = 16; o; o >>= 1) {
        so += __shfl_xor_sync(0xffffffffu, so, o);
        sd += __shfl_xor_sync(0xffffffffu, sd, o);
    }
    if (lane == 0) {
        out[w]          = so + ob2[0];
        out[Bv*Nv + w]  = sd + db2[0];
    }
}

// ---------------- launcher ----------------
// Slot 4 = fused k_xlxr (l=0) for profile continuity. Dataflow unchanged.
extern "C" void kernel_launch(void* const* d_in, const int* in_sizes, int n_in,
                              void* d_out, int out_size) {
    const float* x   = (const float*)d_in[0];
    const int*   ei  = (const int*)  d_in[1];
    const float* ea  = (const float*)d_in[2];
    const float* Wp  = (const float*)d_in[3];
    const float* bp  = (const float*)d_in[4];
    const float* Wl  = (const float*)d_in[5];
    const float* bl  = (const float*)d_in[6];
    const float* Wr  = (const float*)d_in[7];
    const float* br  = (const float*)d_in[8];
    const float* We  = (const float*)d_in[9];
    const float* att = (const float*)d_in[10];
    const float* gb  = (const float*)d_in[11];
    const float* Wih = (const float*)d_in[12];
    const float* Whh = (const float*)d_in[13];
    const float* bih = (const float*)d_in[14];
    const float* bhh = (const float*)d_in[15];
    const float* oW1 = (const float*)d_in[16];
    const float* ob1 = (const float*)d_in[17];
    const float* oW2 = (const float*)d_in[18];
    const float* ob2 = (const float*)d_in[19];
    const float* dW1 = (const float*)d_in[20];
    const float* db1 = (const float*)d_in[21];
    const float* dW2 = (const float*)d_in[22];
    const float* db2 = (const float*)d_in[23];
    float* out = (float*)d_out;

    // 1-3: input-only deps
    k_proj    <<<GN/32, 256>>>(x, Wp, bp);
    k_pack_gru<<<32, 256>>>(Wih, Whh);
    k_zero    <<<8, 256>>>();
    // 4: layer-0 XL/XR projection  <-- ncu capture target
    k_xlxr    <<<GN/32, 256>>>(Wl, bl, Wr, br, 0);
    // deterministic CSR + loop attrs
    k_deg     <<<64, 256>>>(ei);
    k_scan    <<<1, 1024>>>();
    k_fill_csr<<<64, 256>>>(ei);
    k_sort_csr<<<8, 256>>>();
    k_loopattr<<<64, 256>>>(ea);

    for (int l = 0; l < Lv; l++) {
        if (l > 0) k_xlxr<<<GN/32, 256>>>(Wl, bl, Wr, br, l);
        k_ep    <<<E2v*Hv/256, 256>>>(ea, We, l);
        k_logits<<<(int)((size_t)Gv*E2v*32/256), 256>>>(ei, att, l);
        k_aggr  <<<GN*32/256, 256>>>(ei, gb, l);
        k_gru   <<<SNv/16, 256>>>(bih, bhh, l);
    }

    k_heads<<<Bv*Nv*32/256, 256>>>(oW1, ob1, oW2, ob2, dW1, db1, dW2, db2, out);
}